// round 8
// baseline (speedup 1.0000x reference)
#include <cuda_runtime.h>
#include <cuda_fp16.h>
#include <cstdint>
#include <math.h>

#define NL   16
#define HD   128
#define BT   128
#define TBND 3.0f
#define MINWC 0.001f
#define MINHC 0.001f
#define MINDC 0.001f
#define SQH  11.313708498984761f
#define LU_EPS 0.001f
#define LCN  40
#define PSS  25
#define NMM  (NL * 5)
#define ASTR 136                           // act row stride in halves (68 words)

// ---- smem byte offsets ----
#define SM_W0    0                         // 32KB packed fp16 frags
#define SM_W1    32768
#define SM_ACT0  65536                     // 128*136*2 = 34816
#define SM_ACT1  100352
#define SM_PS    135168                    // 128*25*4 = 12800
#define SM_SCR   147968                    // 27*128*4 = 13824
#define SM_OUT0  161792                    // 512
#define SM_TOTAL 162304

__device__ float g_lconst[NL * LCN];
__device__ uint4 g_wpack[NMM * 2048];      // [m][ks(8)][mt_abs(8)][lane(32)] fp16 A-frags

// ============================ helpers ============================
__device__ __forceinline__ uint32_t smem_u32(const void* p) {
    uint32_t a;
    asm("{ .reg .u64 t; cvta.to.shared.u64 t, %1; cvt.u32.u64 %0, t; }" : "=r"(a) : "l"(p));
    return a;
}
__device__ __forceinline__ uint32_t pack_h2(float lo, float hi) {
    __half2 h = __floats2half2_rn(lo, hi);
    return *(uint32_t*)&h;
}
__device__ __forceinline__ void mma_f16(float* d, const uint4 a, const uint32_t b0,
                                        const uint32_t b1) {
    asm volatile("mma.sync.aligned.m16n8k16.row.col.f32.f16.f16.f32 "
        "{%0,%1,%2,%3}, {%4,%5,%6,%7}, {%8,%9}, {%0,%1,%2,%3};"
        : "+f"(d[0]), "+f"(d[1]), "+f"(d[2]), "+f"(d[3])
        : "r"(a.x), "r"(a.y), "r"(a.z), "r"(a.w), "r"(b0), "r"(b1));
}
__device__ __forceinline__ void stage_pack(uint32_t sdst, const uint4* __restrict__ src, int tid) {
    #pragma unroll
    for (int i = 0; i < 4; i++) {
        int c = i * 512 + tid;
        asm volatile("cp.async.cg.shared.global [%0], [%1], 16;"
                     :: "r"(sdst + (uint32_t)c * 16u), "l"(src + c) : "memory");
    }
    asm volatile("cp.async.commit_group;" ::: "memory");
}
#define CP_WAIT0() asm volatile("cp.async.wait_group 0;" ::: "memory")

// store fp16(v) at logical (j=hidden, e=element) into transposed act[e][j]
__device__ __forceinline__ void store_act(uint32_t bufAddr, int j, int e, float v) {
    uint16_t hv = __half_as_ushort(__float2half_rn(v));
    asm volatile("st.shared.u16 [%0], %1;"
                 :: "r"(bufAddr + (uint32_t)(e * ASTR + j) * 2u), "h"(hv) : "memory");
}

__device__ __forceinline__ float softplusf(float v) {
    return (v > 0.f) ? (v + log1pf(expf(-v))) : log1pf(expf(v));
}
__device__ __forceinline__ float siluf(float v) { return v / (1.f + expf(-v)); }

__device__ __forceinline__ void build_knots(float* c, int st, const float* u, int ust,
                                            float inv_scale, float minv) {
    float uw[8]; float m = -1e30f;
    #pragma unroll
    for (int k = 0; k < 8; k++) { uw[k] = u[k * ust] * inv_scale; m = fmaxf(m, uw[k]); }
    float ex[8]; float s = 0.f;
    #pragma unroll
    for (int k = 0; k < 8; k++) { ex[k] = expf(uw[k] - m); s += ex[k]; }
    float sc = (1.f - minv * 8.f) / s;
    float run = 0.f;
    c[0] = -TBND;
    #pragma unroll
    for (int k = 0; k < 8; k++) { run += minv + sc * ex[k]; c[(k + 1) * st] = 2.f * TBND * run - TBND; }
    c[8 * st] = TBND;
}

__device__ __forceinline__ float2 rqs_inv(float y, const float* cw, const float* ch,
                                          const float* d, int st) {
    bool inside = (y >= -TBND) && (y <= TBND);
    float yc = fminf(fmaxf(y, -TBND), TBND);
    int idx = 0;
    #pragma unroll
    for (int m = 1; m < 8; m++) idx += (yc >= ch[m * st]) ? 1 : 0;
    float yk  = ch[idx * st];
    float hk  = ch[(idx + 1) * st] - yk;
    float xk  = cw[idx * st];
    float wk  = cw[(idx + 1) * st] - xk;
    float dk  = d[idx * st];
    float dk1 = d[(idx + 1) * st];
    float sk = hk / wk;
    float dy = yc - yk;
    float t2 = dk + dk1 - 2.f * sk;
    float a = dy * t2 + hk * (sk - dk);
    float b = hk * dk - dy * t2;
    float c = -sk * dy;
    float disc = fmaxf(b * b - 4.f * a * c, 0.f);
    float theta = (2.f * c) / (-b - sqrtf(disc));
    float xo = theta * wk + xk;
    float om = 1.f - theta;
    float denom = sk + t2 * theta * om;
    float dnum = sk * sk * (dk1 * theta * theta + 2.f * sk * theta * om + dk * om * om);
    float ldf = logf(dnum) - 2.f * logf(denom);
    float2 r;
    r.x = inside ? xo : y;
    r.y = inside ? -ldf : 0.f;
    return r;
}

__global__ void precompute_consts_kernel(const float* __restrict__ made_bf,
                                         const float* __restrict__ lu_lower,
                                         const float* __restrict__ lu_upper,
                                         const float* __restrict__ lu_diag,
                                         const float* __restrict__ lu_bias,
                                         const int*   __restrict__ perms) {
    int i = threadIdx.x;
    if (i >= NL) return;
    const float* bf = made_bf + i * 46;
    float* C = g_lconst + i * LCN;
    build_knots(C + 0, 1, bf + 8, 1, 1.f / SQH, MINHC);
    build_knots(C + 9, 1, bf + 0, 1, 1.f / SQH, MINWC);
    C[18] = 1.0f; C[26] = 1.0f;
    for (int k = 1; k < 8; k++) C[18 + k] = MINDC + softplusf(bf[16 + k - 1]);
    float d0 = softplusf(lu_diag[2 * i + 0]) + LU_EPS;
    float d1 = softplusf(lu_diag[2 * i + 1]) + LU_EPS;
    float l = lu_lower[i], u = lu_upper[i];
    float invdet = 1.f / (d0 * d1);
    C[27] = (l * u + d1) * invdet;
    C[28] = -u * invdet;
    C[29] = -l * d0 * invdet;
    C[30] = d0 * invdet;
    C[31] = lu_bias[2 * i + 0];
    C[32] = lu_bias[2 * i + 1];
    C[33] = logf(d0) + logf(d1);
    C[34] = (float)perms[2 * i];
}

// Pack weights into fp16 A-fragment order: g_wpack[m*2048 + ((ks*8+mt)*32+lane)]
__global__ void pack_weights_kernel(const float* __restrict__ made_Wres,
                                    const float* __restrict__ made_Wf) {
    int m = blockIdx.x;
    int L = m / 5, t = m % 5;
    for (int i = threadIdx.x; i < 2048; i += blockDim.x) {
        int ks = i >> 8, mt = (i >> 5) & 7, lane = i & 31;
        int gid = lane >> 2, tig = lane & 3;
        int j = mt * 16 + gid;
        int k = ks * 16 + 2 * tig;
        uint4 u;
        if (t < 4) {
            const float* W = made_Wres + ((long)(L * 4 + t) * HD * HD);
            u.x = pack_h2(__ldg(&W[j * HD + k]),           __ldg(&W[j * HD + k + 1]));
            u.y = pack_h2(__ldg(&W[(j + 8) * HD + k]),     __ldg(&W[(j + 8) * HD + k + 1]));
            u.z = pack_h2(__ldg(&W[j * HD + k + 8]),       __ldg(&W[j * HD + k + 9]));
            u.w = pack_h2(__ldg(&W[(j + 8) * HD + k + 8]), __ldg(&W[(j + 8) * HD + k + 9]));
        } else {
            const float* W = made_Wf + ((long)L * 46 + 23) * HD;
            bool v0 = (j < 23), v1 = (j + 8 < 23);
            u.x = pack_h2(v0 ? __ldg(&W[j * HD + k]) : 0.f,           v0 ? __ldg(&W[j * HD + k + 1]) : 0.f);
            u.y = pack_h2(v1 ? __ldg(&W[(j + 8) * HD + k]) : 0.f,     v1 ? __ldg(&W[(j + 8) * HD + k + 1]) : 0.f);
            u.z = pack_h2(v0 ? __ldg(&W[j * HD + k + 8]) : 0.f,       v0 ? __ldg(&W[j * HD + k + 9]) : 0.f);
            u.w = pack_h2(v1 ? __ldg(&W[(j + 8) * HD + k + 8]) : 0.f, v1 ? __ldg(&W[(j + 8) * HD + k + 9]) : 0.f);
        }
        g_wpack[(long)m * 2048 + i] = u;
    }
}

__global__ void __launch_bounds__(512, 1)
nsf_mma_kernel(const float* __restrict__ z_0, const float* __restrict__ x,
               const float* __restrict__ sigma,
               const float* __restrict__ n1_w1, const float* __restrict__ n1_b1,
               const float* __restrict__ n1_w2, const float* __restrict__ n1_b2,
               const float* __restrict__ n2_w1, const float* __restrict__ n2_b1,
               const float* __restrict__ n2_w2, const float* __restrict__ n2_b2,
               const float* __restrict__ made_W0, const float* __restrict__ made_b0,
               const float* __restrict__ made_bres,
               const float* __restrict__ made_bf,
               float* __restrict__ out, int B) {
    extern __shared__ char smem[];
    float* psm  = (float*)(smem + SM_PS);
    float* out0 = (float*)(smem + SM_OUT0);

    int tid = threadIdx.x;
    int wid = tid >> 5, lane = tid & 31;
    int gid = lane >> 2, tig = lane & 3;
    int jh = wid >> 3, eq = wid & 7;       // jh in {0,1}: 64 rows; eq in {0..7}: 16 cols
    int j_base = jh * 64, e_base = eq * 16;

    long g = (long)blockIdx.x * BT + tid;
    bool lead = (tid < BT) && (g < B);
    float z0r = 0.f, z1r = 0.f, ldr = 0.f, out0r = 0.f;

    // ---- initial conditioning MLPs ----
    if (lead) {
        float sg = sigma[g];
        float tc0 = __ldg(&n1_b2[0]), tc1 = __ldg(&n1_b2[1]);
        #pragma unroll 4
        for (int i = 0; i < 32; i++) {
            float hv = siluf(sg * __ldg(&n1_w1[i]) + __ldg(&n1_b1[i]));
            tc0 += __ldg(&n1_w2[i]) * hv;
            tc1 += __ldg(&n1_w2[32 + i]) * hv;
        }
        float in0 = z_0[2 * g], in1 = z_0[2 * g + 1], in2 = x[2 * g], in3 = x[2 * g + 1];
        float a0 = __ldg(&n2_b2[0]) + tc0, a1 = __ldg(&n2_b2[1]) + tc1;
        #pragma unroll 4
        for (int i = 0; i < 32; i++) {
            float hv = siluf(__ldg(&n2_w1[4 * i]) * in0 + __ldg(&n2_w1[4 * i + 1]) * in1 +
                             __ldg(&n2_w1[4 * i + 2]) * in2 + __ldg(&n2_w1[4 * i + 3]) * in3 +
                             __ldg(&n2_b1[i]));
            a0 += __ldg(&n2_w2[i]) * hv;
            a1 += __ldg(&n2_w2[32 + i]) * hv;
        }
        z0r = a0; z1r = a1;
    }

    uint32_t sb = smem_u32(smem);
    uint32_t actAddr[2] = { sb + SM_ACT0, sb + SM_ACT1 };
    const uint32_t* actWp[2] = { (const uint32_t*)(smem + SM_ACT0),
                                 (const uint32_t*)(smem + SM_ACT1) };
    stage_pack(sb + SM_W0, g_wpack, tid);   // prefetch matmul 0

    float h[4][2][4];
    int m = 0;

    for (int L = 0; L < NL; L++) {
        const float* C = g_lconst + L * LCN;

        // ---- scalar A: dim-0 spline with constant params ----
        if (tid < BT) {
            float2 s0 = rqs_inv(z0r, C + 9, C + 0, C + 18, 1);
            out0r = s0.x; ldr += s0.y;
            out0[tid] = s0.x;
        }
        __syncthreads();

        // ---- h init in frag-layout registers + write act = relu(h) into rd-buffer ----
        {
            uint32_t hbuf = actAddr[m & 1];
            float w0v[4][2], b0v[4][2];
            #pragma unroll
            for (int mt = 0; mt < 4; mt++)
                #pragma unroll
                for (int rh = 0; rh < 2; rh++) {
                    int j = j_base + mt * 16 + gid + rh * 8;
                    w0v[mt][rh] = __ldg(&made_W0[(long)L * HD * 2 + j * 2]);
                    b0v[mt][rh] = __ldg(&made_b0[(long)L * HD + j]);
                }
            #pragma unroll
            for (int mt = 0; mt < 4; mt++)
                #pragma unroll
                for (int nt = 0; nt < 2; nt++)
                    #pragma unroll
                    for (int r = 0; r < 4; r++) {
                        int rh = r >> 1;
                        int j = j_base + mt * 16 + gid + rh * 8;
                        int e = e_base + nt * 8 + 2 * tig + (r & 1);
                        float hv = fmaf(out0[e], w0v[mt][rh], b0v[mt][rh]);
                        h[mt][nt][r] = hv;
                        store_act(hbuf, j, e, fmaxf(hv, 0.f));
                    }
        }

        // ---- 5 matmuls: W1..W4 (128x128), Wf (23x128 padded) ----
        for (int mm = 0; mm < 5; mm++) {
            CP_WAIT0();
            __syncthreads();   // weights[m] staged; act writes (epilogue/h-init) visible

            if (m + 1 < NMM) {
                uint32_t dst = sb + (((m + 1) & 1) ? SM_W1 : SM_W0);
                stage_pack(dst, g_wpack + (long)(m + 1) * 2048, tid);
            }

            const uint4* Wsm = (const uint4*)(smem + ((m & 1) ? SM_W1 : SM_W0));
            const uint32_t* actRd = actWp[m & 1];
            uint32_t wrBuf = actAddr[(m + 1) & 1];

            if (mm < 4) {
                float d[4][2][4];
                #pragma unroll
                for (int mt = 0; mt < 4; mt++)
                    #pragma unroll
                    for (int nt = 0; nt < 2; nt++)
                        #pragma unroll
                        for (int r = 0; r < 4; r++) d[mt][nt][r] = 0.f;

                #pragma unroll
                for (int ks = 0; ks < 8; ks++) {
                    uint4 a[4];
                    #pragma unroll
                    for (int mt = 0; mt < 4; mt++)
                        a[mt] = Wsm[(ks * 8 + jh * 4 + mt) * 32 + lane];
                    uint32_t b0[2], b1[2];
                    #pragma unroll
                    for (int nt = 0; nt < 2; nt++) {
                        int e = e_base + nt * 8 + gid;
                        int w = e * (ASTR / 2) + ks * 8 + tig;
                        b0[nt] = actRd[w];
                        b1[nt] = actRd[w + 4];
                    }
                    #pragma unroll
                    for (int mt = 0; mt < 4; mt++)
                        #pragma unroll
                        for (int nt = 0; nt < 2; nt++)
                            mma_f16(d[mt][nt], a[mt], b0[nt], b1[nt]);
                }

                float bja[4][2];
                #pragma unroll
                for (int mt = 0; mt < 4; mt++)
                    #pragma unroll
                    for (int rh = 0; rh < 2; rh++)
                        bja[mt][rh] = __ldg(&made_bres[((long)L * 4 + mm) * HD +
                                                       j_base + mt * 16 + gid + rh * 8]);
                #pragma unroll
                for (int mt = 0; mt < 4; mt++)
                    #pragma unroll
                    for (int nt = 0; nt < 2; nt++)
                        #pragma unroll
                        for (int r = 0; r < 4; r++) {
                            int rh = r >> 1;
                            int j = j_base + mt * 16 + gid + rh * 8;
                            int e = e_base + nt * 8 + 2 * tig + (r & 1);
                            float dv = d[mt][nt][r] + bja[mt][rh];
                            float sv;
                            if (mm == 0 || mm == 2) {
                                sv = fmaxf(dv, 0.f);
                            } else {
                                h[mt][nt][r] += dv;
                                sv = (mm == 1) ? fmaxf(h[mt][nt][r], 0.f) : h[mt][nt][r];
                            }
                            store_act(wrBuf, j, e, sv);
                        }
            } else {
                // p-projection: warp w covers e in [8w, 8w+8), rows 0..31 (23 valid)
                float d[2][4];
                #pragma unroll
                for (int mt = 0; mt < 2; mt++)
                    #pragma unroll
                    for (int r = 0; r < 4; r++) d[mt][r] = 0.f;

                #pragma unroll
                for (int ks = 0; ks < 8; ks++) {
                    uint4 a[2];
                    a[0] = Wsm[(ks * 8 + 0) * 32 + lane];
                    a[1] = Wsm[(ks * 8 + 1) * 32 + lane];
                    int e = wid * 8 + gid;
                    int w = e * (ASTR / 2) + ks * 8 + tig;
                    uint32_t b0 = actRd[w], b1 = actRd[w + 4];
                    mma_f16(d[0], a[0], b0, b1);
                    mma_f16(d[1], a[1], b0, b1);
                }

                #pragma unroll
                for (int mt = 0; mt < 2; mt++)
                    #pragma unroll
                    for (int r = 0; r < 4; r++) {
                        int j = mt * 16 + gid + ((r >> 1) ? 8 : 0);
                        if (j < 23) {
                            float pb = __ldg(&made_bf[(long)L * 46 + 23 + j]);
                            int e = wid * 8 + 2 * tig + (r & 1);
                            psm[e * PSS + j] = d[mt][r] + pb;
                        }
                    }
            }
            m++;
        }
        __syncthreads();   // psm complete

        // ---- scalar B: dim-1 spline + LU solve + permutation ----
        if (tid < BT) {
            float p[23];
            #pragma unroll
            for (int k = 0; k < 23; k++) p[k] = psm[tid * PSS + k];
            float* scr = (float*)(smem + SM_SCR);
            float* chp = scr + tid;
            float* cwp = scr + 9 * BT + tid;
            float* dp  = scr + 18 * BT + tid;
            build_knots(chp, BT, p + 8, 1, 1.f / SQH, MINHC);
            build_knots(cwp, BT, p + 0, 1, 1.f / SQH, MINWC);
            dp[0] = 1.0f; dp[8 * BT] = 1.0f;
            #pragma unroll
            for (int k = 1; k < 8; k++) dp[k * BT] = MINDC + softplusf(p[15 + k]);
            float2 s1 = rqs_inv(z1r, cwp, chp, dp, BT);
            ldr += s1.y;
            float v0 = out0r - C[31];
            float v1 = s1.x - C[32];
            float zn0 = C[27] * v0 + C[28] * v1;
            float zn1 = C[29] * v0 + C[30] * v1;
            ldr -= C[33];
            if (C[34] != 0.f) { float t = zn0; zn0 = zn1; zn1 = t; }
            z0r = zn0; z1r = zn1;
        }
        __syncthreads();
    }

    if (lead) {
        out[2 * g]     = z0r;
        out[2 * g + 1] = z1r;
        out[(long)2 * B + g] = ldr;
    }
}

extern "C" void kernel_launch(void* const* d_in, const int* in_sizes, int n_in,
                              void* d_out, int out_size) {
    const float* z_0      = (const float*)d_in[0];
    const float* x        = (const float*)d_in[1];
    const float* sigma    = (const float*)d_in[2];
    const float* n1_w1    = (const float*)d_in[3];
    const float* n1_b1    = (const float*)d_in[4];
    const float* n1_w2    = (const float*)d_in[5];
    const float* n1_b2    = (const float*)d_in[6];
    const float* n2_w1    = (const float*)d_in[7];
    const float* n2_b1    = (const float*)d_in[8];
    const float* n2_w2    = (const float*)d_in[9];
    const float* n2_b2    = (const float*)d_in[10];
    const float* made_W0  = (const float*)d_in[11];
    const float* made_b0  = (const float*)d_in[12];
    const float* made_Wres= (const float*)d_in[13];
    const float* made_bres= (const float*)d_in[14];
    const float* made_Wf  = (const float*)d_in[15];
    const float* made_bf  = (const float*)d_in[16];
    const float* lu_lower = (const float*)d_in[17];
    const float* lu_upper = (const float*)d_in[18];
    const float* lu_diag  = (const float*)d_in[19];
    const float* lu_bias  = (const float*)d_in[20];
    const int*   perms    = (const int*)d_in[21];

    int B = in_sizes[0] / 2;

    precompute_consts_kernel<<<1, 32>>>(made_bf, lu_lower, lu_upper, lu_diag, lu_bias, perms);
    pack_weights_kernel<<<NMM, 256>>>(made_Wres, made_Wf);

    cudaFuncSetAttribute(nsf_mma_kernel, cudaFuncAttributeMaxDynamicSharedMemorySize, SM_TOTAL);
    int grid = (B + BT - 1) / BT;
    nsf_mma_kernel<<<grid, 512, SM_TOTAL>>>(z_0, x, sigma,
                                            n1_w1, n1_b1, n1_w2, n1_b2,
                                            n2_w1, n2_b1, n2_w2, n2_b2,
                                            made_W0, made_b0, made_bres,
                                            made_bf,
                                            (float*)d_out, B);
}

// round 9
// speedup vs baseline: 1.0178x; 1.0178x over previous
#include <cuda_runtime.h>
#include <cuda_fp16.h>
#include <cstdint>
#include <math.h>

#define NL   16
#define HD   128
#define BT   128
#define TBND 3.0f
#define MINWC 0.001f
#define MINHC 0.001f
#define MINDC 0.001f
#define SQH  11.313708498984761f
#define LU_EPS 0.001f
#define LCN  40
#define PSS  25
#define NMM  (NL * 5)
#define ASTR 136                           // act row stride in halves (68 words)

// ---- smem byte offsets ----
#define SM_W0    0                         // 32KB packed fp16 frags
#define SM_W1    32768
#define SM_ACT0  65536                     // 128*136*2 = 34816
#define SM_ACT1  100352
#define SM_PS    135168                    // 128*25*4 = 12800
#define SM_SCR   147968                    // 27*128*4 = 13824
#define SM_OUT0  161792                    // 512
#define SM_TOTAL 162304

__device__ float g_lconst[NL * LCN];
__device__ uint4 g_wpack[NMM * 2048];      // [m][ks(8)][mt_abs(8)][lane(32)] fp16 A-frags

// ============================ helpers ============================
__device__ __forceinline__ uint32_t smem_u32(const void* p) {
    uint32_t a;
    asm("{ .reg .u64 t; cvta.to.shared.u64 t, %1; cvt.u32.u64 %0, t; }" : "=r"(a) : "l"(p));
    return a;
}
__device__ __forceinline__ uint32_t pack_h2(float lo, float hi) {
    __half2 h = __floats2half2_rn(lo, hi);
    return *(uint32_t*)&h;
}
__device__ __forceinline__ void mma_f16(float* d, const uint4 a, const uint32_t b0,
                                        const uint32_t b1) {
    asm volatile("mma.sync.aligned.m16n8k16.row.col.f32.f16.f16.f32 "
        "{%0,%1,%2,%3}, {%4,%5,%6,%7}, {%8,%9}, {%0,%1,%2,%3};"
        : "+f"(d[0]), "+f"(d[1]), "+f"(d[2]), "+f"(d[3])
        : "r"(a.x), "r"(a.y), "r"(a.z), "r"(a.w), "r"(b0), "r"(b1));
}
__device__ __forceinline__ void stage_pack(uint32_t sdst, const uint4* __restrict__ src, int tid) {
    #pragma unroll
    for (int i = 0; i < 4; i++) {
        int c = i * 512 + tid;
        asm volatile("cp.async.cg.shared.global [%0], [%1], 16;"
                     :: "r"(sdst + (uint32_t)c * 16u), "l"(src + c) : "memory");
    }
    asm volatile("cp.async.commit_group;" ::: "memory");
}
#define CP_WAIT0() asm volatile("cp.async.wait_group 0;" ::: "memory")

// store fp16(v) at logical (j=hidden, e=element) into transposed act[e][j]
__device__ __forceinline__ void store_act(uint32_t bufAddr, int j, int e, float v) {
    uint16_t hv = __half_as_ushort(__float2half_rn(v));
    asm volatile("st.shared.u16 [%0], %1;"
                 :: "r"(bufAddr + (uint32_t)(e * ASTR + j) * 2u), "h"(hv) : "memory");
}

__device__ __forceinline__ float softplusf(float v) {
    return (v > 0.f) ? (v + log1pf(expf(-v))) : log1pf(expf(v));
}
__device__ __forceinline__ float siluf(float v) { return v / (1.f + expf(-v)); }

__device__ __forceinline__ void build_knots(float* c, int st, const float* u, int ust,
                                            float inv_scale, float minv) {
    float uw[8]; float m = -1e30f;
    #pragma unroll
    for (int k = 0; k < 8; k++) { uw[k] = u[k * ust] * inv_scale; m = fmaxf(m, uw[k]); }
    float ex[8]; float s = 0.f;
    #pragma unroll
    for (int k = 0; k < 8; k++) { ex[k] = expf(uw[k] - m); s += ex[k]; }
    float sc = (1.f - minv * 8.f) / s;
    float run = 0.f;
    c[0] = -TBND;
    #pragma unroll
    for (int k = 0; k < 8; k++) { run += minv + sc * ex[k]; c[(k + 1) * st] = 2.f * TBND * run - TBND; }
    c[8 * st] = TBND;
}

__device__ __forceinline__ float2 rqs_inv(float y, const float* cw, const float* ch,
                                          const float* d, int st) {
    bool inside = (y >= -TBND) && (y <= TBND);
    float yc = fminf(fmaxf(y, -TBND), TBND);
    int idx = 0;
    #pragma unroll
    for (int m = 1; m < 8; m++) idx += (yc >= ch[m * st]) ? 1 : 0;
    float yk  = ch[idx * st];
    float hk  = ch[(idx + 1) * st] - yk;
    float xk  = cw[idx * st];
    float wk  = cw[(idx + 1) * st] - xk;
    float dk  = d[idx * st];
    float dk1 = d[(idx + 1) * st];
    float sk = hk / wk;
    float dy = yc - yk;
    float t2 = dk + dk1 - 2.f * sk;
    float a = dy * t2 + hk * (sk - dk);
    float b = hk * dk - dy * t2;
    float c = -sk * dy;
    float disc = fmaxf(b * b - 4.f * a * c, 0.f);
    float theta = (2.f * c) / (-b - sqrtf(disc));
    float xo = theta * wk + xk;
    float om = 1.f - theta;
    float denom = sk + t2 * theta * om;
    float dnum = sk * sk * (dk1 * theta * theta + 2.f * sk * theta * om + dk * om * om);
    float ldf = logf(dnum) - 2.f * logf(denom);
    float2 r;
    r.x = inside ? xo : y;
    r.y = inside ? -ldf : 0.f;
    return r;
}

__global__ void precompute_consts_kernel(const float* __restrict__ made_bf,
                                         const float* __restrict__ lu_lower,
                                         const float* __restrict__ lu_upper,
                                         const float* __restrict__ lu_diag,
                                         const float* __restrict__ lu_bias,
                                         const int*   __restrict__ perms) {
    int i = threadIdx.x;
    if (i >= NL) return;
    const float* bf = made_bf + i * 46;
    float* C = g_lconst + i * LCN;
    build_knots(C + 0, 1, bf + 8, 1, 1.f / SQH, MINHC);
    build_knots(C + 9, 1, bf + 0, 1, 1.f / SQH, MINWC);
    C[18] = 1.0f; C[26] = 1.0f;
    for (int k = 1; k < 8; k++) C[18 + k] = MINDC + softplusf(bf[16 + k - 1]);
    float d0 = softplusf(lu_diag[2 * i + 0]) + LU_EPS;
    float d1 = softplusf(lu_diag[2 * i + 1]) + LU_EPS;
    float l = lu_lower[i], u = lu_upper[i];
    float invdet = 1.f / (d0 * d1);
    C[27] = (l * u + d1) * invdet;
    C[28] = -u * invdet;
    C[29] = -l * d0 * invdet;
    C[30] = d0 * invdet;
    C[31] = lu_bias[2 * i + 0];
    C[32] = lu_bias[2 * i + 1];
    C[33] = logf(d0) + logf(d1);
    C[34] = (float)perms[2 * i];
}

// Pack weights into fp16 A-fragment order: g_wpack[m*2048 + ((ks*8+mt)*32+lane)]
__global__ void pack_weights_kernel(const float* __restrict__ made_Wres,
                                    const float* __restrict__ made_Wf) {
    int m = blockIdx.x;
    int L = m / 5, t = m % 5;
    for (int i = threadIdx.x; i < 2048; i += blockDim.x) {
        int ks = i >> 8, mt = (i >> 5) & 7, lane = i & 31;
        int gid = lane >> 2, tig = lane & 3;
        int j = mt * 16 + gid;
        int k = ks * 16 + 2 * tig;
        uint4 u;
        if (t < 4) {
            const float* W = made_Wres + ((long)(L * 4 + t) * HD * HD);
            u.x = pack_h2(__ldg(&W[j * HD + k]),           __ldg(&W[j * HD + k + 1]));
            u.y = pack_h2(__ldg(&W[(j + 8) * HD + k]),     __ldg(&W[(j + 8) * HD + k + 1]));
            u.z = pack_h2(__ldg(&W[j * HD + k + 8]),       __ldg(&W[j * HD + k + 9]));
            u.w = pack_h2(__ldg(&W[(j + 8) * HD + k + 8]), __ldg(&W[(j + 8) * HD + k + 9]));
        } else {
            const float* W = made_Wf + ((long)L * 46 + 23) * HD;
            bool v0 = (j < 23), v1 = (j + 8 < 23);
            u.x = pack_h2(v0 ? __ldg(&W[j * HD + k]) : 0.f,           v0 ? __ldg(&W[j * HD + k + 1]) : 0.f);
            u.y = pack_h2(v1 ? __ldg(&W[(j + 8) * HD + k]) : 0.f,     v1 ? __ldg(&W[(j + 8) * HD + k + 1]) : 0.f);
            u.z = pack_h2(v0 ? __ldg(&W[j * HD + k + 8]) : 0.f,       v0 ? __ldg(&W[j * HD + k + 9]) : 0.f);
            u.w = pack_h2(v1 ? __ldg(&W[(j + 8) * HD + k + 8]) : 0.f, v1 ? __ldg(&W[(j + 8) * HD + k + 9]) : 0.f);
        }
        g_wpack[(long)m * 2048 + i] = u;
    }
}

__global__ void __launch_bounds__(512, 1)
nsf_mma_kernel(const float* __restrict__ z_0, const float* __restrict__ x,
               const float* __restrict__ sigma,
               const float* __restrict__ n1_w1, const float* __restrict__ n1_b1,
               const float* __restrict__ n1_w2, const float* __restrict__ n1_b2,
               const float* __restrict__ n2_w1, const float* __restrict__ n2_b1,
               const float* __restrict__ n2_w2, const float* __restrict__ n2_b2,
               const float* __restrict__ made_W0, const float* __restrict__ made_b0,
               const float* __restrict__ made_bres,
               const float* __restrict__ made_bf,
               float* __restrict__ out, int B) {
    extern __shared__ char smem[];
    float* psm  = (float*)(smem + SM_PS);
    float* out0 = (float*)(smem + SM_OUT0);

    int tid = threadIdx.x;
    int wid = tid >> 5, lane = tid & 31;
    int gid = lane >> 2, tig = lane & 3;
    int jh = wid >> 2, eq = wid & 3;       // 32j x 32e per warp (balanced tile)
    int j_base = jh * 32, e_base = eq * 32;

    long g = (long)blockIdx.x * BT + tid;
    bool lead = (tid < BT) && (g < B);
    float z0r = 0.f, z1r = 0.f, ldr = 0.f, out0r = 0.f;

    // ---- initial conditioning MLPs ----
    if (lead) {
        float sg = sigma[g];
        float tc0 = __ldg(&n1_b2[0]), tc1 = __ldg(&n1_b2[1]);
        #pragma unroll 4
        for (int i = 0; i < 32; i++) {
            float hv = siluf(sg * __ldg(&n1_w1[i]) + __ldg(&n1_b1[i]));
            tc0 += __ldg(&n1_w2[i]) * hv;
            tc1 += __ldg(&n1_w2[32 + i]) * hv;
        }
        float in0 = z_0[2 * g], in1 = z_0[2 * g + 1], in2 = x[2 * g], in3 = x[2 * g + 1];
        float a0 = __ldg(&n2_b2[0]) + tc0, a1 = __ldg(&n2_b2[1]) + tc1;
        #pragma unroll 4
        for (int i = 0; i < 32; i++) {
            float hv = siluf(__ldg(&n2_w1[4 * i]) * in0 + __ldg(&n2_w1[4 * i + 1]) * in1 +
                             __ldg(&n2_w1[4 * i + 2]) * in2 + __ldg(&n2_w1[4 * i + 3]) * in3 +
                             __ldg(&n2_b1[i]));
            a0 += __ldg(&n2_w2[i]) * hv;
            a1 += __ldg(&n2_w2[32 + i]) * hv;
        }
        z0r = a0; z1r = a1;
    }

    uint32_t sb = smem_u32(smem);
    uint32_t actAddr[2] = { sb + SM_ACT0, sb + SM_ACT1 };
    const uint32_t* actWp[2] = { (const uint32_t*)(smem + SM_ACT0),
                                 (const uint32_t*)(smem + SM_ACT1) };
    stage_pack(sb + SM_W0, g_wpack, tid);   // prefetch matmul 0

    float h[2][4][4];
    int m = 0;

    for (int L = 0; L < NL; L++) {
        const float* C = g_lconst + L * LCN;

        // ---- scalar A: dim-0 spline with constant params ----
        if (tid < BT) {
            float2 s0 = rqs_inv(z0r, C + 9, C + 0, C + 18, 1);
            out0r = s0.x; ldr += s0.y;
            out0[tid] = s0.x;
        }
        __syncthreads();

        // ---- h init in frag-layout registers + write act = relu(h) into rd-buffer ----
        {
            uint32_t hbuf = actAddr[m & 1];
            float w0v[2][2], b0v[2][2];
            #pragma unroll
            for (int mt = 0; mt < 2; mt++)
                #pragma unroll
                for (int rh = 0; rh < 2; rh++) {
                    int j = j_base + mt * 16 + gid + rh * 8;
                    w0v[mt][rh] = __ldg(&made_W0[(long)L * HD * 2 + j * 2]);
                    b0v[mt][rh] = __ldg(&made_b0[(long)L * HD + j]);
                }
            #pragma unroll
            for (int mt = 0; mt < 2; mt++)
                #pragma unroll
                for (int nt = 0; nt < 4; nt++)
                    #pragma unroll
                    for (int r = 0; r < 4; r++) {
                        int rh = r >> 1;
                        int j = j_base + mt * 16 + gid + rh * 8;
                        int e = e_base + nt * 8 + 2 * tig + (r & 1);
                        float hv = fmaf(out0[e], w0v[mt][rh], b0v[mt][rh]);
                        h[mt][nt][r] = hv;
                        store_act(hbuf, j, e, fmaxf(hv, 0.f));
                    }
        }

        // ---- 5 matmuls: W1..W4 (128x128), Wf (23x128 padded) ----
        for (int mm = 0; mm < 5; mm++) {
            CP_WAIT0();
            __syncthreads();   // weights[m] staged; act writes (epilogue/h-init) visible

            if (m + 1 < NMM) {
                uint32_t dst = sb + (((m + 1) & 1) ? SM_W1 : SM_W0);
                stage_pack(dst, g_wpack + (long)(m + 1) * 2048, tid);
            }

            const uint4* Wsm = (const uint4*)(smem + ((m & 1) ? SM_W1 : SM_W0));
            const uint32_t* actRd = actWp[m & 1];
            uint32_t wrBuf = actAddr[(m + 1) & 1];

            if (mm < 4) {
                float d[2][4][4];
                #pragma unroll
                for (int mt = 0; mt < 2; mt++)
                    #pragma unroll
                    for (int nt = 0; nt < 4; nt++)
                        #pragma unroll
                        for (int r = 0; r < 4; r++) d[mt][nt][r] = 0.f;

                #pragma unroll
                for (int ks = 0; ks < 8; ks++) {
                    uint4 a[2];
                    a[0] = Wsm[(ks * 8 + jh * 2 + 0) * 32 + lane];
                    a[1] = Wsm[(ks * 8 + jh * 2 + 1) * 32 + lane];
                    uint32_t b0[4], b1[4];
                    #pragma unroll
                    for (int nt = 0; nt < 4; nt++) {
                        int e = e_base + nt * 8 + gid;
                        int w = e * (ASTR / 2) + ks * 8 + tig;
                        b0[nt] = actRd[w];
                        b1[nt] = actRd[w + 4];
                    }
                    #pragma unroll
                    for (int mt = 0; mt < 2; mt++)
                        #pragma unroll
                        for (int nt = 0; nt < 4; nt++)
                            mma_f16(d[mt][nt], a[mt], b0[nt], b1[nt]);
                }

                float bja[2][2];
                #pragma unroll
                for (int mt = 0; mt < 2; mt++)
                    #pragma unroll
                    for (int rh = 0; rh < 2; rh++)
                        bja[mt][rh] = __ldg(&made_bres[((long)L * 4 + mm) * HD +
                                                       j_base + mt * 16 + gid + rh * 8]);
                #pragma unroll
                for (int mt = 0; mt < 2; mt++)
                    #pragma unroll
                    for (int nt = 0; nt < 4; nt++)
                        #pragma unroll
                        for (int r = 0; r < 4; r++) {
                            int rh = r >> 1;
                            int j = j_base + mt * 16 + gid + rh * 8;
                            int e = e_base + nt * 8 + 2 * tig + (r & 1);
                            float dv = d[mt][nt][r] + bja[mt][rh];
                            float sv;
                            if (mm == 0 || mm == 2) {
                                sv = fmaxf(dv, 0.f);
                            } else {
                                h[mt][nt][r] += dv;
                                sv = (mm == 1) ? fmaxf(h[mt][nt][r], 0.f) : h[mt][nt][r];
                            }
                            store_act(wrBuf, j, e, sv);
                        }
            } else {
                // p-projection: warp w covers e in [8w, 8w+8), rows 0..31 (23 valid)
                float d[2][4];
                #pragma unroll
                for (int mt = 0; mt < 2; mt++)
                    #pragma unroll
                    for (int r = 0; r < 4; r++) d[mt][r] = 0.f;

                #pragma unroll
                for (int ks = 0; ks < 8; ks++) {
                    uint4 a[2];
                    a[0] = Wsm[(ks * 8 + 0) * 32 + lane];
                    a[1] = Wsm[(ks * 8 + 1) * 32 + lane];
                    int e = wid * 8 + gid;
                    int w = e * (ASTR / 2) + ks * 8 + tig;
                    uint32_t b0 = actRd[w], b1 = actRd[w + 4];
                    mma_f16(d[0], a[0], b0, b1);
                    mma_f16(d[1], a[1], b0, b1);
                }

                #pragma unroll
                for (int mt = 0; mt < 2; mt++)
                    #pragma unroll
                    for (int r = 0; r < 4; r++) {
                        int j = mt * 16 + gid + ((r >> 1) ? 8 : 0);
                        if (j < 23) {
                            float pb = __ldg(&made_bf[(long)L * 46 + 23 + j]);
                            int e = wid * 8 + 2 * tig + (r & 1);
                            psm[e * PSS + j] = d[mt][r] + pb;
                        }
                    }
            }
            m++;
        }
        __syncthreads();   // psm complete

        // ---- scalar B: dim-1 spline + LU solve + permutation ----
        if (tid < BT) {
            float p[23];
            #pragma unroll
            for (int k = 0; k < 23; k++) p[k] = psm[tid * PSS + k];
            float* scr = (float*)(smem + SM_SCR);
            float* chp = scr + tid;
            float* cwp = scr + 9 * BT + tid;
            float* dp  = scr + 18 * BT + tid;
            build_knots(chp, BT, p + 8, 1, 1.f / SQH, MINHC);
            build_knots(cwp, BT, p + 0, 1, 1.f / SQH, MINWC);
            dp[0] = 1.0f; dp[8 * BT] = 1.0f;
            #pragma unroll
            for (int k = 1; k < 8; k++) dp[k * BT] = MINDC + softplusf(p[15 + k]);
            float2 s1 = rqs_inv(z1r, cwp, chp, dp, BT);
            ldr += s1.y;
            float v0 = out0r - C[31];
            float v1 = s1.x - C[32];
            float zn0 = C[27] * v0 + C[28] * v1;
            float zn1 = C[29] * v0 + C[30] * v1;
            ldr -= C[33];
            if (C[34] != 0.f) { float t = zn0; zn0 = zn1; zn1 = t; }
            z0r = zn0; z1r = zn1;
        }
        __syncthreads();
    }

    if (lead) {
        out[2 * g]     = z0r;
        out[2 * g + 1] = z1r;
        out[(long)2 * B + g] = ldr;
    }
}

extern "C" void kernel_launch(void* const* d_in, const int* in_sizes, int n_in,
                              void* d_out, int out_size) {
    const float* z_0      = (const float*)d_in[0];
    const float* x        = (const float*)d_in[1];
    const float* sigma    = (const float*)d_in[2];
    const float* n1_w1    = (const float*)d_in[3];
    const float* n1_b1    = (const float*)d_in[4];
    const float* n1_w2    = (const float*)d_in[5];
    const float* n1_b2    = (const float*)d_in[6];
    const float* n2_w1    = (const float*)d_in[7];
    const float* n2_b1    = (const float*)d_in[8];
    const float* n2_w2    = (const float*)d_in[9];
    const float* n2_b2    = (const float*)d_in[10];
    const float* made_W0  = (const float*)d_in[11];
    const float* made_b0  = (const float*)d_in[12];
    const float* made_Wres= (const float*)d_in[13];
    const float* made_bres= (const float*)d_in[14];
    const float* made_Wf  = (const float*)d_in[15];
    const float* made_bf  = (const float*)d_in[16];
    const float* lu_lower = (const float*)d_in[17];
    const float* lu_upper = (const float*)d_in[18];
    const float* lu_diag  = (const float*)d_in[19];
    const float* lu_bias  = (const float*)d_in[20];
    const int*   perms    = (const int*)d_in[21];

    int B = in_sizes[0] / 2;

    precompute_consts_kernel<<<1, 32>>>(made_bf, lu_lower, lu_upper, lu_diag, lu_bias, perms);
    pack_weights_kernel<<<NMM, 256>>>(made_Wres, made_Wf);

    cudaFuncSetAttribute(nsf_mma_kernel, cudaFuncAttributeMaxDynamicSharedMemorySize, SM_TOTAL);
    int grid = (B + BT - 1) / BT;
    nsf_mma_kernel<<<grid, 512, SM_TOTAL>>>(z_0, x, sigma,
                                            n1_w1, n1_b1, n1_w2, n1_b2,
                                            n2_w1, n2_b1, n2_w2, n2_b2,
                                            made_W0, made_b0, made_bres,
                                            made_bf,
                                            (float*)d_out, B);
}

// round 10
// speedup vs baseline: 1.1650x; 1.1447x over previous
#include <cuda_runtime.h>
#include <cuda_fp16.h>
#include <cstdint>
#include <math.h>

#define NL   16
#define HD   128
#define BT   64
#define TBND 3.0f
#define MINWC 0.001f
#define MINHC 0.001f
#define MINDC 0.001f
#define SQH  11.313708498984761f
#define LU_EPS 0.001f
#define LCN  40
#define PSS  25
#define NMM  (NL * 5)
#define ASTR 136                           // act row stride in halves (68 words)

// ---- smem byte offsets (per CTA; 2 CTAs/SM) ----
#define SM_W0    0                         // 32KB packed fp16 frags
#define SM_W1    32768
#define SM_ACT   65536                     // 64*136*2 = 17408
#define SM_PS    82944                     // 64*25*4 = 6400
#define SM_SCR   89344                     // 27*64*4 = 6912
#define SM_OUT0  96256                     // 256
#define SM_TOTAL 96512

__device__ float g_lconst[NL * LCN];
__device__ uint4 g_wpack[NMM * 2048];      // [m][ks(8)][mt_abs(8)][lane(32)] fp16 A-frags

// ============================ helpers ============================
__device__ __forceinline__ uint32_t smem_u32(const void* p) {
    uint32_t a;
    asm("{ .reg .u64 t; cvta.to.shared.u64 t, %1; cvt.u32.u64 %0, t; }" : "=r"(a) : "l"(p));
    return a;
}
__device__ __forceinline__ uint32_t pack_h2(float lo, float hi) {
    __half2 h = __floats2half2_rn(lo, hi);
    return *(uint32_t*)&h;
}
__device__ __forceinline__ void mma_f16(float* d, const uint4 a, const uint32_t b0,
                                        const uint32_t b1) {
    asm volatile("mma.sync.aligned.m16n8k16.row.col.f32.f16.f16.f32 "
        "{%0,%1,%2,%3}, {%4,%5,%6,%7}, {%8,%9}, {%0,%1,%2,%3};"
        : "+f"(d[0]), "+f"(d[1]), "+f"(d[2]), "+f"(d[3])
        : "r"(a.x), "r"(a.y), "r"(a.z), "r"(a.w), "r"(b0), "r"(b1));
}
__device__ __forceinline__ void stage_pack(uint32_t sdst, const uint4* __restrict__ src, int tid) {
    #pragma unroll
    for (int i = 0; i < 8; i++) {
        int c = i * 256 + tid;
        asm volatile("cp.async.cg.shared.global [%0], [%1], 16;"
                     :: "r"(sdst + (uint32_t)c * 16u), "l"(src + c) : "memory");
    }
    asm volatile("cp.async.commit_group;" ::: "memory");
}
#define CP_WAIT0() asm volatile("cp.async.wait_group 0;" ::: "memory")

// store fp16(v) at logical (j=hidden, e=element) into transposed act[e][j]
__device__ __forceinline__ void store_act(uint32_t actBase, int j, int e, float v) {
    uint16_t hv = __half_as_ushort(__float2half_rn(v));
    asm volatile("st.shared.u16 [%0], %1;"
                 :: "r"(actBase + (uint32_t)(e * ASTR + j) * 2u), "h"(hv) : "memory");
}

__device__ __forceinline__ float softplusf(float v) {
    return (v > 0.f) ? (v + log1pf(expf(-v))) : log1pf(expf(v));
}
__device__ __forceinline__ float siluf(float v) { return v / (1.f + expf(-v)); }

__device__ __forceinline__ void build_knots(float* c, int st, const float* u, int ust,
                                            float inv_scale, float minv) {
    float uw[8]; float m = -1e30f;
    #pragma unroll
    for (int k = 0; k < 8; k++) { uw[k] = u[k * ust] * inv_scale; m = fmaxf(m, uw[k]); }
    float ex[8]; float s = 0.f;
    #pragma unroll
    for (int k = 0; k < 8; k++) { ex[k] = expf(uw[k] - m); s += ex[k]; }
    float sc = (1.f - minv * 8.f) / s;
    float run = 0.f;
    c[0] = -TBND;
    #pragma unroll
    for (int k = 0; k < 8; k++) { run += minv + sc * ex[k]; c[(k + 1) * st] = 2.f * TBND * run - TBND; }
    c[8 * st] = TBND;
}

__device__ __forceinline__ float2 rqs_inv(float y, const float* cw, const float* ch,
                                          const float* d, int st) {
    bool inside = (y >= -TBND) && (y <= TBND);
    float yc = fminf(fmaxf(y, -TBND), TBND);
    int idx = 0;
    #pragma unroll
    for (int m = 1; m < 8; m++) idx += (yc >= ch[m * st]) ? 1 : 0;
    float yk  = ch[idx * st];
    float hk  = ch[(idx + 1) * st] - yk;
    float xk  = cw[idx * st];
    float wk  = cw[(idx + 1) * st] - xk;
    float dk  = d[idx * st];
    float dk1 = d[(idx + 1) * st];
    float sk = hk / wk;
    float dy = yc - yk;
    float t2 = dk + dk1 - 2.f * sk;
    float a = dy * t2 + hk * (sk - dk);
    float b = hk * dk - dy * t2;
    float c = -sk * dy;
    float disc = fmaxf(b * b - 4.f * a * c, 0.f);
    float theta = (2.f * c) / (-b - sqrtf(disc));
    float xo = theta * wk + xk;
    float om = 1.f - theta;
    float denom = sk + t2 * theta * om;
    float dnum = sk * sk * (dk1 * theta * theta + 2.f * sk * theta * om + dk * om * om);
    float ldf = logf(dnum) - 2.f * logf(denom);
    float2 r;
    r.x = inside ? xo : y;
    r.y = inside ? -ldf : 0.f;
    return r;
}

__global__ void precompute_consts_kernel(const float* __restrict__ made_bf,
                                         const float* __restrict__ lu_lower,
                                         const float* __restrict__ lu_upper,
                                         const float* __restrict__ lu_diag,
                                         const float* __restrict__ lu_bias,
                                         const int*   __restrict__ perms) {
    int i = threadIdx.x;
    if (i >= NL) return;
    const float* bf = made_bf + i * 46;
    float* C = g_lconst + i * LCN;
    build_knots(C + 0, 1, bf + 8, 1, 1.f / SQH, MINHC);
    build_knots(C + 9, 1, bf + 0, 1, 1.f / SQH, MINWC);
    C[18] = 1.0f; C[26] = 1.0f;
    for (int k = 1; k < 8; k++) C[18 + k] = MINDC + softplusf(bf[16 + k - 1]);
    float d0 = softplusf(lu_diag[2 * i + 0]) + LU_EPS;
    float d1 = softplusf(lu_diag[2 * i + 1]) + LU_EPS;
    float l = lu_lower[i], u = lu_upper[i];
    float invdet = 1.f / (d0 * d1);
    C[27] = (l * u + d1) * invdet;
    C[28] = -u * invdet;
    C[29] = -l * d0 * invdet;
    C[30] = d0 * invdet;
    C[31] = lu_bias[2 * i + 0];
    C[32] = lu_bias[2 * i + 1];
    C[33] = logf(d0) + logf(d1);
    C[34] = (float)perms[2 * i];
}

// Pack weights into fp16 A-fragment order: g_wpack[m*2048 + ((ks*8+mt)*32+lane)]
__global__ void pack_weights_kernel(const float* __restrict__ made_Wres,
                                    const float* __restrict__ made_Wf) {
    int m = blockIdx.x;
    int L = m / 5, t = m % 5;
    for (int i = threadIdx.x; i < 2048; i += blockDim.x) {
        int ks = i >> 8, mt = (i >> 5) & 7, lane = i & 31;
        int gid = lane >> 2, tig = lane & 3;
        int j = mt * 16 + gid;
        int k = ks * 16 + 2 * tig;
        uint4 u;
        if (t < 4) {
            const float* W = made_Wres + ((long)(L * 4 + t) * HD * HD);
            u.x = pack_h2(__ldg(&W[j * HD + k]),           __ldg(&W[j * HD + k + 1]));
            u.y = pack_h2(__ldg(&W[(j + 8) * HD + k]),     __ldg(&W[(j + 8) * HD + k + 1]));
            u.z = pack_h2(__ldg(&W[j * HD + k + 8]),       __ldg(&W[j * HD + k + 9]));
            u.w = pack_h2(__ldg(&W[(j + 8) * HD + k + 8]), __ldg(&W[(j + 8) * HD + k + 9]));
        } else {
            const float* W = made_Wf + ((long)L * 46 + 23) * HD;
            bool v0 = (j < 23), v1 = (j + 8 < 23);
            u.x = pack_h2(v0 ? __ldg(&W[j * HD + k]) : 0.f,           v0 ? __ldg(&W[j * HD + k + 1]) : 0.f);
            u.y = pack_h2(v1 ? __ldg(&W[(j + 8) * HD + k]) : 0.f,     v1 ? __ldg(&W[(j + 8) * HD + k + 1]) : 0.f);
            u.z = pack_h2(v0 ? __ldg(&W[j * HD + k + 8]) : 0.f,       v0 ? __ldg(&W[j * HD + k + 9]) : 0.f);
            u.w = pack_h2(v1 ? __ldg(&W[(j + 8) * HD + k + 8]) : 0.f, v1 ? __ldg(&W[(j + 8) * HD + k + 9]) : 0.f);
        }
        g_wpack[(long)m * 2048 + i] = u;
    }
}

__global__ void __launch_bounds__(256, 2)
nsf_mma_kernel(const float* __restrict__ z_0, const float* __restrict__ x,
               const float* __restrict__ sigma,
               const float* __restrict__ n1_w1, const float* __restrict__ n1_b1,
               const float* __restrict__ n1_w2, const float* __restrict__ n1_b2,
               const float* __restrict__ n2_w1, const float* __restrict__ n2_b1,
               const float* __restrict__ n2_w2, const float* __restrict__ n2_b2,
               const float* __restrict__ made_W0, const float* __restrict__ made_b0,
               const float* __restrict__ made_bres,
               const float* __restrict__ made_bf,
               float* __restrict__ out, int B) {
    extern __shared__ char smem[];
    const uint32_t* actW = (const uint32_t*)(smem + SM_ACT);
    float* psm  = (float*)(smem + SM_PS);
    float* out0 = (float*)(smem + SM_OUT0);

    int tid = threadIdx.x;
    int wid = tid >> 5, lane = tid & 31;
    int gid = lane >> 2, tig = lane & 3;
    int jh = wid >> 1, eq = wid & 1;       // 32j x 32e per warp (balanced tile)
    int j_base = jh * 32, e_base = eq * 32;

    long g = (long)blockIdx.x * BT + tid;
    bool lead = (tid < BT) && (g < B);
    float z0r = 0.f, z1r = 0.f, ldr = 0.f, out0r = 0.f;

    // ---- initial conditioning MLPs ----
    if (lead) {
        float sg = sigma[g];
        float tc0 = __ldg(&n1_b2[0]), tc1 = __ldg(&n1_b2[1]);
        #pragma unroll 4
        for (int i = 0; i < 32; i++) {
            float hv = siluf(sg * __ldg(&n1_w1[i]) + __ldg(&n1_b1[i]));
            tc0 += __ldg(&n1_w2[i]) * hv;
            tc1 += __ldg(&n1_w2[32 + i]) * hv;
        }
        float in0 = z_0[2 * g], in1 = z_0[2 * g + 1], in2 = x[2 * g], in3 = x[2 * g + 1];
        float a0 = __ldg(&n2_b2[0]) + tc0, a1 = __ldg(&n2_b2[1]) + tc1;
        #pragma unroll 4
        for (int i = 0; i < 32; i++) {
            float hv = siluf(__ldg(&n2_w1[4 * i]) * in0 + __ldg(&n2_w1[4 * i + 1]) * in1 +
                             __ldg(&n2_w1[4 * i + 2]) * in2 + __ldg(&n2_w1[4 * i + 3]) * in3 +
                             __ldg(&n2_b1[i]));
            a0 += __ldg(&n2_w2[i]) * hv;
            a1 += __ldg(&n2_w2[32 + i]) * hv;
        }
        z0r = a0; z1r = a1;
    }

    uint32_t sb = smem_u32(smem);
    uint32_t actBase = sb + SM_ACT;
    stage_pack(sb + SM_W0, g_wpack, tid);   // prefetch matmul 0

    float h[2][4][4];
    int m = 0;

    for (int L = 0; L < NL; L++) {
        const float* C = g_lconst + L * LCN;

        // ---- scalar A: dim-0 spline with constant params ----
        if (tid < BT) {
            float2 s0 = rqs_inv(z0r, C + 9, C + 0, C + 18, 1);
            out0r = s0.x; ldr += s0.y;
            out0[tid] = s0.x;
        }
        __syncthreads();

        // ---- h init in frag-layout registers + write act = relu(h) ----
        {
            float w0v[2][2], b0v[2][2];
            #pragma unroll
            for (int mt = 0; mt < 2; mt++)
                #pragma unroll
                for (int rh = 0; rh < 2; rh++) {
                    int j = j_base + mt * 16 + gid + rh * 8;
                    w0v[mt][rh] = __ldg(&made_W0[(long)L * HD * 2 + j * 2]);
                    b0v[mt][rh] = __ldg(&made_b0[(long)L * HD + j]);
                }
            #pragma unroll
            for (int mt = 0; mt < 2; mt++)
                #pragma unroll
                for (int nt = 0; nt < 4; nt++)
                    #pragma unroll
                    for (int r = 0; r < 4; r++) {
                        int rh = r >> 1;
                        int j = j_base + mt * 16 + gid + rh * 8;
                        int e = e_base + nt * 8 + 2 * tig + (r & 1);
                        float hv = fmaf(out0[e], w0v[mt][rh], b0v[mt][rh]);
                        h[mt][nt][r] = hv;
                        store_act(actBase, j, e, fmaxf(hv, 0.f));
                    }
        }

        // ---- 5 matmuls: W1..W4 (128x128 over 64 elems), Wf (23x128 padded) ----
        for (int mm = 0; mm < 5; mm++) {
            CP_WAIT0();
            __syncthreads();   // W[m] ready; act writes visible

            if (m + 1 < NMM) {
                uint32_t dst = sb + (((m + 1) & 1) ? SM_W1 : SM_W0);
                stage_pack(dst, g_wpack + (long)(m + 1) * 2048, tid);
            }

            const uint4* Wsm = (const uint4*)(smem + ((m & 1) ? SM_W1 : SM_W0));

            if (mm < 4) {
                float d[2][4][4];
                #pragma unroll
                for (int mt = 0; mt < 2; mt++)
                    #pragma unroll
                    for (int nt = 0; nt < 4; nt++)
                        #pragma unroll
                        for (int r = 0; r < 4; r++) d[mt][nt][r] = 0.f;

                #pragma unroll
                for (int ks = 0; ks < 8; ks++) {
                    uint4 a[2];
                    a[0] = Wsm[(ks * 8 + jh * 2 + 0) * 32 + lane];
                    a[1] = Wsm[(ks * 8 + jh * 2 + 1) * 32 + lane];
                    uint32_t b0[4], b1[4];
                    #pragma unroll
                    for (int nt = 0; nt < 4; nt++) {
                        int e = e_base + nt * 8 + gid;
                        int w = e * (ASTR / 2) + ks * 8 + tig;
                        b0[nt] = actW[w];
                        b1[nt] = actW[w + 4];
                    }
                    #pragma unroll
                    for (int mt = 0; mt < 2; mt++)
                        #pragma unroll
                        for (int nt = 0; nt < 4; nt++)
                            mma_f16(d[mt][nt], a[mt], b0[nt], b1[nt]);
                }
                __syncthreads();   // all act reads done before overwrite

                float bja[2][2];
                #pragma unroll
                for (int mt = 0; mt < 2; mt++)
                    #pragma unroll
                    for (int rh = 0; rh < 2; rh++)
                        bja[mt][rh] = __ldg(&made_bres[((long)L * 4 + mm) * HD +
                                                       j_base + mt * 16 + gid + rh * 8]);
                #pragma unroll
                for (int mt = 0; mt < 2; mt++)
                    #pragma unroll
                    for (int nt = 0; nt < 4; nt++)
                        #pragma unroll
                        for (int r = 0; r < 4; r++) {
                            int rh = r >> 1;
                            int j = j_base + mt * 16 + gid + rh * 8;
                            int e = e_base + nt * 8 + 2 * tig + (r & 1);
                            float dv = d[mt][nt][r] + bja[mt][rh];
                            float sv;
                            if (mm == 0 || mm == 2) {
                                sv = fmaxf(dv, 0.f);
                            } else {
                                h[mt][nt][r] += dv;
                                sv = (mm == 1) ? fmaxf(h[mt][nt][r], 0.f) : h[mt][nt][r];
                            }
                            store_act(actBase, j, e, sv);
                        }
            } else {
                // p-projection: warp w covers e in [8w, 8w+8), rows 0..31 (23 valid)
                float d[2][4];
                #pragma unroll
                for (int mt = 0; mt < 2; mt++)
                    #pragma unroll
                    for (int r = 0; r < 4; r++) d[mt][r] = 0.f;

                #pragma unroll
                for (int ks = 0; ks < 8; ks++) {
                    uint4 a[2];
                    a[0] = Wsm[(ks * 8 + 0) * 32 + lane];
                    a[1] = Wsm[(ks * 8 + 1) * 32 + lane];
                    int e = wid * 8 + gid;
                    int w = e * (ASTR / 2) + ks * 8 + tig;
                    uint32_t b0 = actW[w], b1 = actW[w + 4];
                    mma_f16(d[0], a[0], b0, b1);
                    mma_f16(d[1], a[1], b0, b1);
                }
                __syncthreads();

                #pragma unroll
                for (int mt = 0; mt < 2; mt++)
                    #pragma unroll
                    for (int r = 0; r < 4; r++) {
                        int j = mt * 16 + gid + ((r >> 1) ? 8 : 0);
                        if (j < 23) {
                            float pb = __ldg(&made_bf[(long)L * 46 + 23 + j]);
                            int e = wid * 8 + 2 * tig + (r & 1);
                            psm[e * PSS + j] = d[mt][r] + pb;
                        }
                    }
            }
            m++;
        }
        __syncthreads();   // psm complete

        // ---- scalar B: dim-1 spline + LU solve + permutation ----
        if (tid < BT) {
            float p[23];
            #pragma unroll
            for (int k = 0; k < 23; k++) p[k] = psm[tid * PSS + k];
            float* scr = (float*)(smem + SM_SCR);
            float* chp = scr + tid;
            float* cwp = scr + 9 * BT + tid;
            float* dp  = scr + 18 * BT + tid;
            build_knots(chp, BT, p + 8, 1, 1.f / SQH, MINHC);
            build_knots(cwp, BT, p + 0, 1, 1.f / SQH, MINWC);
            dp[0] = 1.0f; dp[8 * BT] = 1.0f;
            #pragma unroll
            for (int k = 1; k < 8; k++) dp[k * BT] = MINDC + softplusf(p[15 + k]);
            float2 s1 = rqs_inv(z1r, cwp, chp, dp, BT);
            ldr += s1.y;
            float v0 = out0r - C[31];
            float v1 = s1.x - C[32];
            float zn0 = C[27] * v0 + C[28] * v1;
            float zn1 = C[29] * v0 + C[30] * v1;
            ldr -= C[33];
            if (C[34] != 0.f) { float t = zn0; zn0 = zn1; zn1 = t; }
            z0r = zn0; z1r = zn1;
        }
        __syncthreads();
    }

    if (lead) {
        out[2 * g]     = z0r;
        out[2 * g + 1] = z1r;
        out[(long)2 * B + g] = ldr;
    }
}

extern "C" void kernel_launch(void* const* d_in, const int* in_sizes, int n_in,
                              void* d_out, int out_size) {
    const float* z_0      = (const float*)d_in[0];
    const float* x        = (const float*)d_in[1];
    const float* sigma    = (const float*)d_in[2];
    const float* n1_w1    = (const float*)d_in[3];
    const float* n1_b1    = (const float*)d_in[4];
    const float* n1_w2    = (const float*)d_in[5];
    const float* n1_b2    = (const float*)d_in[6];
    const float* n2_w1    = (const float*)d_in[7];
    const float* n2_b1    = (const float*)d_in[8];
    const float* n2_w2    = (const float*)d_in[9];
    const float* n2_b2    = (const float*)d_in[10];
    const float* made_W0  = (const float*)d_in[11];
    const float* made_b0  = (const float*)d_in[12];
    const float* made_Wres= (const float*)d_in[13];
    const float* made_bres= (const float*)d_in[14];
    const float* made_Wf  = (const float*)d_in[15];
    const float* made_bf  = (const float*)d_in[16];
    const float* lu_lower = (const float*)d_in[17];
    const float* lu_upper = (const float*)d_in[18];
    const float* lu_diag  = (const float*)d_in[19];
    const float* lu_bias  = (const float*)d_in[20];
    const int*   perms    = (const int*)d_in[21];

    int B = in_sizes[0] / 2;

    precompute_consts_kernel<<<1, 32>>>(made_bf, lu_lower, lu_upper, lu_diag, lu_bias, perms);
    pack_weights_kernel<<<NMM, 256>>>(made_Wres, made_Wf);

    cudaFuncSetAttribute(nsf_mma_kernel, cudaFuncAttributeMaxDynamicSharedMemorySize, SM_TOTAL);
    int grid = (B + BT - 1) / BT;
    nsf_mma_kernel<<<grid, 256, SM_TOTAL>>>(z_0, x, sigma,
                                            n1_w1, n1_b1, n1_w2, n1_b2,
                                            n2_w1, n2_b1, n2_w2, n2_b2,
                                            made_W0, made_b0, made_bres,
                                            made_bf,
                                            (float*)d_out, B);
}

// round 12
// speedup vs baseline: 1.1706x; 1.0048x over previous
#include <cuda_runtime.h>
#include <cuda_fp16.h>
#include <cstdint>
#include <math.h>

#define NL   16
#define HD   128
#define BT   64
#define TBND 3.0f
#define MINWC 0.001f
#define MINHC 0.001f
#define MINDC 0.001f
#define SQH  11.313708498984761f
#define LU_EPS 0.001f
#define LCN  40
#define PSS  25
#define NMM  (NL * 5)
#define ASTR 136                           // act row stride in halves (68 words)

// ---- smem byte offsets (per CTA; 2 CTAs/SM) ----
#define SM_ACT   0                         // 64*136*2 = 17408
#define SM_PS    17408                     // 64*25*4 = 6400
#define SM_SCR   23808                     // 27*64*4 = 6912
#define SM_OUT0  30720                     // 256
#define SM_TOTAL 30976

__device__ float g_lconst[NL * LCN];
__device__ uint4 g_wpack[NMM * 2048];      // [m][ks(8)][mt_abs(8)][lane(32)] fp16 A-frags

// ============================ helpers ============================
__device__ __forceinline__ uint32_t smem_u32(const void* p) {
    uint32_t a;
    asm("{ .reg .u64 t; cvta.to.shared.u64 t, %1; cvt.u32.u64 %0, t; }" : "=r"(a) : "l"(p));
    return a;
}
__device__ __forceinline__ uint32_t pack_h2(float lo, float hi) {
    __half2 h = __floats2half2_rn(lo, hi);
    return *(uint32_t*)&h;
}
__device__ __forceinline__ void mma_f16(float* d, const uint4 a, const uint32_t b0,
                                        const uint32_t b1) {
    asm volatile("mma.sync.aligned.m16n8k16.row.col.f32.f16.f16.f32 "
        "{%0,%1,%2,%3}, {%4,%5,%6,%7}, {%8,%9}, {%0,%1,%2,%3};"
        : "+f"(d[0]), "+f"(d[1]), "+f"(d[2]), "+f"(d[3])
        : "r"(a.x), "r"(a.y), "r"(a.z), "r"(a.w), "r"(b0), "r"(b1));
}

// store fp16(v) at logical (j=hidden, e=element) into transposed act[e][j]
__device__ __forceinline__ void store_act(uint32_t actBase, int j, int e, float v) {
    uint16_t hv = __half_as_ushort(__float2half_rn(v));
    asm volatile("st.shared.u16 [%0], %1;"
                 :: "r"(actBase + (uint32_t)(e * ASTR + j) * 2u), "h"(hv) : "memory");
}

__device__ __forceinline__ float softplusf(float v) {
    return (v > 0.f) ? (v + log1pf(expf(-v))) : log1pf(expf(v));
}
__device__ __forceinline__ float siluf(float v) { return v / (1.f + expf(-v)); }

__device__ __forceinline__ void build_knots(float* c, int st, const float* u, int ust,
                                            float inv_scale, float minv) {
    float uw[8]; float m = -1e30f;
    #pragma unroll
    for (int k = 0; k < 8; k++) { uw[k] = u[k * ust] * inv_scale; m = fmaxf(m, uw[k]); }
    float ex[8]; float s = 0.f;
    #pragma unroll
    for (int k = 0; k < 8; k++) { ex[k] = expf(uw[k] - m); s += ex[k]; }
    float sc = (1.f - minv * 8.f) / s;
    float run = 0.f;
    c[0] = -TBND;
    #pragma unroll
    for (int k = 0; k < 8; k++) { run += minv + sc * ex[k]; c[(k + 1) * st] = 2.f * TBND * run - TBND; }
    c[8 * st] = TBND;
}

__device__ __forceinline__ float2 rqs_inv(float y, const float* cw, const float* ch,
                                          const float* d, int st) {
    bool inside = (y >= -TBND) && (y <= TBND);
    float yc = fminf(fmaxf(y, -TBND), TBND);
    int idx = 0;
    #pragma unroll
    for (int m = 1; m < 8; m++) idx += (yc >= ch[m * st]) ? 1 : 0;
    float yk  = ch[idx * st];
    float hk  = ch[(idx + 1) * st] - yk;
    float xk  = cw[idx * st];
    float wk  = cw[(idx + 1) * st] - xk;
    float dk  = d[idx * st];
    float dk1 = d[(idx + 1) * st];
    float sk = hk / wk;
    float dy = yc - yk;
    float t2 = dk + dk1 - 2.f * sk;
    float a = dy * t2 + hk * (sk - dk);
    float b = hk * dk - dy * t2;
    float c = -sk * dy;
    float disc = fmaxf(b * b - 4.f * a * c, 0.f);
    float theta = (2.f * c) / (-b - sqrtf(disc));
    float xo = theta * wk + xk;
    float om = 1.f - theta;
    float denom = sk + t2 * theta * om;
    float dnum = sk * sk * (dk1 * theta * theta + 2.f * sk * theta * om + dk * om * om);
    float ldf = logf(dnum) - 2.f * logf(denom);
    float2 r;
    r.x = inside ? xo : y;
    r.y = inside ? -ldf : 0.f;
    return r;
}

__global__ void precompute_consts_kernel(const float* __restrict__ made_bf,
                                         const float* __restrict__ lu_lower,
                                         const float* __restrict__ lu_upper,
                                         const float* __restrict__ lu_diag,
                                         const float* __restrict__ lu_bias,
                                         const int*   __restrict__ perms) {
    int i = threadIdx.x;
    if (i >= NL) return;
    const float* bf = made_bf + i * 46;
    float* C = g_lconst + i * LCN;
    build_knots(C + 0, 1, bf + 8, 1, 1.f / SQH, MINHC);
    build_knots(C + 9, 1, bf + 0, 1, 1.f / SQH, MINWC);
    C[18] = 1.0f; C[26] = 1.0f;
    for (int k = 1; k < 8; k++) C[18 + k] = MINDC + softplusf(bf[16 + k - 1]);
    float d0 = softplusf(lu_diag[2 * i + 0]) + LU_EPS;
    float d1 = softplusf(lu_diag[2 * i + 1]) + LU_EPS;
    float l = lu_lower[i], u = lu_upper[i];
    float invdet = 1.f / (d0 * d1);
    C[27] = (l * u + d1) * invdet;
    C[28] = -u * invdet;
    C[29] = -l * d0 * invdet;
    C[30] = d0 * invdet;
    C[31] = lu_bias[2 * i + 0];
    C[32] = lu_bias[2 * i + 1];
    C[33] = logf(d0) + logf(d1);
    C[34] = (float)perms[2 * i];
}

// Pack weights into fp16 A-fragment order: g_wpack[m*2048 + ((ks*8+mt)*32+lane)]
__global__ void pack_weights_kernel(const float* __restrict__ made_Wres,
                                    const float* __restrict__ made_Wf) {
    int m = blockIdx.x;
    int L = m / 5, t = m % 5;
    for (int i = threadIdx.x; i < 2048; i += blockDim.x) {
        int ks = i >> 8, mt = (i >> 5) & 7, lane = i & 31;
        int gid = lane >> 2, tig = lane & 3;
        int j = mt * 16 + gid;
        int k = ks * 16 + 2 * tig;
        uint4 u;
        if (t < 4) {
            const float* W = made_Wres + ((long)(L * 4 + t) * HD * HD);
            u.x = pack_h2(__ldg(&W[j * HD + k]),           __ldg(&W[j * HD + k + 1]));
            u.y = pack_h2(__ldg(&W[(j + 8) * HD + k]),     __ldg(&W[(j + 8) * HD + k + 1]));
            u.z = pack_h2(__ldg(&W[j * HD + k + 8]),       __ldg(&W[j * HD + k + 9]));
            u.w = pack_h2(__ldg(&W[(j + 8) * HD + k + 8]), __ldg(&W[(j + 8) * HD + k + 9]));
        } else {
            const float* W = made_Wf + ((long)L * 46 + 23) * HD;
            bool v0 = (j < 23), v1 = (j + 8 < 23);
            u.x = pack_h2(v0 ? __ldg(&W[j * HD + k]) : 0.f,           v0 ? __ldg(&W[j * HD + k + 1]) : 0.f);
            u.y = pack_h2(v1 ? __ldg(&W[(j + 8) * HD + k]) : 0.f,     v1 ? __ldg(&W[(j + 8) * HD + k + 1]) : 0.f);
            u.z = pack_h2(v0 ? __ldg(&W[j * HD + k + 8]) : 0.f,       v0 ? __ldg(&W[j * HD + k + 9]) : 0.f);
            u.w = pack_h2(v1 ? __ldg(&W[(j + 8) * HD + k + 8]) : 0.f, v1 ? __ldg(&W[(j + 8) * HD + k + 9]) : 0.f);
        }
        g_wpack[(long)m * 2048 + i] = u;
    }
}

__global__ void __launch_bounds__(256, 2)
nsf_mma_kernel(const float* __restrict__ z_0, const float* __restrict__ x,
               const float* __restrict__ sigma,
               const float* __restrict__ n1_w1, const float* __restrict__ n1_b1,
               const float* __restrict__ n1_w2, const float* __restrict__ n1_b2,
               const float* __restrict__ n2_w1, const float* __restrict__ n2_b1,
               const float* __restrict__ n2_w2, const float* __restrict__ n2_b2,
               const float* __restrict__ made_W0, const float* __restrict__ made_b0,
               const float* __restrict__ made_bres,
               const float* __restrict__ made_bf,
               float* __restrict__ out, int B) {
    extern __shared__ char smem[];
    const uint32_t* actW = (const uint32_t*)(smem + SM_ACT);
    float* psm  = (float*)(smem + SM_PS);
    float* out0 = (float*)(smem + SM_OUT0);

    int tid = threadIdx.x;
    int wid = tid >> 5, lane = tid & 31;
    int gid = lane >> 2, tig = lane & 3;
    int jh = wid >> 1, eq = wid & 1;       // 32j x 32e per warp (balanced tile)
    int j_base = jh * 32, e_base = eq * 32;

    long g = (long)blockIdx.x * BT + tid;
    bool lead = (tid < BT) && (g < B);
    float z0r = 0.f, z1r = 0.f, ldr = 0.f, out0r = 0.f;

    // ---- initial conditioning MLPs ----
    if (lead) {
        float sg = sigma[g];
        float tc0 = __ldg(&n1_b2[0]), tc1 = __ldg(&n1_b2[1]);
        #pragma unroll 4
        for (int i = 0; i < 32; i++) {
            float hv = siluf(sg * __ldg(&n1_w1[i]) + __ldg(&n1_b1[i]));
            tc0 += __ldg(&n1_w2[i]) * hv;
            tc1 += __ldg(&n1_w2[32 + i]) * hv;
        }
        float in0 = z_0[2 * g], in1 = z_0[2 * g + 1], in2 = x[2 * g], in3 = x[2 * g + 1];
        float a0 = __ldg(&n2_b2[0]) + tc0, a1 = __ldg(&n2_b2[1]) + tc1;
        #pragma unroll 4
        for (int i = 0; i < 32; i++) {
            float hv = siluf(__ldg(&n2_w1[4 * i]) * in0 + __ldg(&n2_w1[4 * i + 1]) * in1 +
                             __ldg(&n2_w1[4 * i + 2]) * in2 + __ldg(&n2_w1[4 * i + 3]) * in3 +
                             __ldg(&n2_b1[i]));
            a0 += __ldg(&n2_w2[i]) * hv;
            a1 += __ldg(&n2_w2[32 + i]) * hv;
        }
        z0r = a0; z1r = a1;
    }

    uint32_t sb = smem_u32(smem);
    uint32_t actBase = sb + SM_ACT;

    float h[2][4][4];
    int m = 0;

    for (int L = 0; L < NL; L++) {
        const float* C = g_lconst + L * LCN;

        // ---- scalar A: dim-0 spline with constant params ----
        if (tid < BT) {
            float2 s0 = rqs_inv(z0r, C + 9, C + 0, C + 18, 1);
            out0r = s0.x; ldr += s0.y;
            out0[tid] = s0.x;
        }
        __syncthreads();

        // ---- h init in frag-layout registers + write act = relu(h) ----
        {
            float w0v[2][2], b0v[2][2];
            #pragma unroll
            for (int mt = 0; mt < 2; mt++)
                #pragma unroll
                for (int rh = 0; rh < 2; rh++) {
                    int j = j_base + mt * 16 + gid + rh * 8;
                    w0v[mt][rh] = __ldg(&made_W0[(long)L * HD * 2 + j * 2]);
                    b0v[mt][rh] = __ldg(&made_b0[(long)L * HD + j]);
                }
            #pragma unroll
            for (int mt = 0; mt < 2; mt++)
                #pragma unroll
                for (int nt = 0; nt < 4; nt++)
                    #pragma unroll
                    for (int r = 0; r < 4; r++) {
                        int rh = r >> 1;
                        int j = j_base + mt * 16 + gid + rh * 8;
                        int e = e_base + nt * 8 + 2 * tig + (r & 1);
                        float hv = fmaf(out0[e], w0v[mt][rh], b0v[mt][rh]);
                        h[mt][nt][r] = hv;
                        store_act(actBase, j, e, fmaxf(hv, 0.f));
                    }
        }
        __syncthreads();   // act writes visible to all warps

        // ---- 5 matmuls: W1..W4 (128x128 over 64 elems), Wf (23x128 padded) ----
        for (int mm = 0; mm < 5; mm++) {
            // A-fragments come straight from g_wpack (L1/L2-resident), no smem staging
            const uint4* Wg = g_wpack + (long)m * 2048;

            if (mm < 4) {
                float d[2][4][4];
                #pragma unroll
                for (int mt = 0; mt < 2; mt++)
                    #pragma unroll
                    for (int nt = 0; nt < 4; nt++)
                        #pragma unroll
                        for (int r = 0; r < 4; r++) d[mt][nt][r] = 0.f;

                #pragma unroll
                for (int ks = 0; ks < 8; ks++) {
                    uint4 a[2];
                    a[0] = __ldg(&Wg[(ks * 8 + jh * 2 + 0) * 32 + lane]);
                    a[1] = __ldg(&Wg[(ks * 8 + jh * 2 + 1) * 32 + lane]);
                    uint32_t b0[4], b1[4];
                    #pragma unroll
                    for (int nt = 0; nt < 4; nt++) {
                        int e = e_base + nt * 8 + gid;
                        int w = e * (ASTR / 2) + ks * 8 + tig;
                        b0[nt] = actW[w];
                        b1[nt] = actW[w + 4];
                    }
                    #pragma unroll
                    for (int mt = 0; mt < 2; mt++)
                        #pragma unroll
                        for (int nt = 0; nt < 4; nt++)
                            mma_f16(d[mt][nt], a[mt], b0[nt], b1[nt]);
                }
                __syncthreads();   // all act reads done before overwrite

                float bja[2][2];
                #pragma unroll
                for (int mt = 0; mt < 2; mt++)
                    #pragma unroll
                    for (int rh = 0; rh < 2; rh++)
                        bja[mt][rh] = __ldg(&made_bres[((long)L * 4 + mm) * HD +
                                                       j_base + mt * 16 + gid + rh * 8]);
                #pragma unroll
                for (int mt = 0; mt < 2; mt++)
                    #pragma unroll
                    for (int nt = 0; nt < 4; nt++)
                        #pragma unroll
                        for (int r = 0; r < 4; r++) {
                            int rh = r >> 1;
                            int j = j_base + mt * 16 + gid + rh * 8;
                            int e = e_base + nt * 8 + 2 * tig + (r & 1);
                            float dv = d[mt][nt][r] + bja[mt][rh];
                            float sv;
                            if (mm == 0 || mm == 2) {
                                sv = fmaxf(dv, 0.f);
                            } else {
                                h[mt][nt][r] += dv;
                                sv = (mm == 1) ? fmaxf(h[mt][nt][r], 0.f) : h[mt][nt][r];
                            }
                            store_act(actBase, j, e, sv);
                        }
                __syncthreads();   // act writes visible before next matmul reads
            } else {
                // p-projection: warp w covers e in [8w, 8w+8), rows 0..31 (23 valid)
                float d[2][4];
                #pragma unroll
                for (int mt = 0; mt < 2; mt++)
                    #pragma unroll
                    for (int r = 0; r < 4; r++) d[mt][r] = 0.f;

                #pragma unroll
                for (int ks = 0; ks < 8; ks++) {
                    uint4 a[2];
                    a[0] = __ldg(&Wg[(ks * 8 + 0) * 32 + lane]);
                    a[1] = __ldg(&Wg[(ks * 8 + 1) * 32 + lane]);
                    int e = wid * 8 + gid;
                    int w = e * (ASTR / 2) + ks * 8 + tig;
                    uint32_t b0 = actW[w], b1 = actW[w + 4];
                    mma_f16(d[0], a[0], b0, b1);
                    mma_f16(d[1], a[1], b0, b1);
                }

                #pragma unroll
                for (int mt = 0; mt < 2; mt++)
                    #pragma unroll
                    for (int r = 0; r < 4; r++) {
                        int j = mt * 16 + gid + ((r >> 1) ? 8 : 0);
                        if (j < 23) {
                            float pb = __ldg(&made_bf[(long)L * 46 + 23 + j]);
                            int e = wid * 8 + 2 * tig + (r & 1);
                            psm[e * PSS + j] = d[mt][r] + pb;
                        }
                    }
            }
            m++;
        }
        __syncthreads();   // psm complete

        // ---- scalar B: dim-1 spline + LU solve + permutation ----
        if (tid < BT) {
            float p[23];
            #pragma unroll
            for (int k = 0; k < 23; k++) p[k] = psm[tid * PSS + k];
            float* scr = (float*)(smem + SM_SCR);
            float* chp = scr + tid;
            float* cwp = scr + 9 * BT + tid;
            float* dp  = scr + 18 * BT + tid;
            build_knots(chp, BT, p + 8, 1, 1.f / SQH, MINHC);
            build_knots(cwp, BT, p + 0, 1, 1.f / SQH, MINWC);
            dp[0] = 1.0f; dp[8 * BT] = 1.0f;
            #pragma unroll
            for (int k = 1; k < 8; k++) dp[k * BT] = MINDC + softplusf(p[15 + k]);
            float2 s1 = rqs_inv(z1r, cwp, chp, dp, BT);
            ldr += s1.y;
            float v0 = out0r - C[31];
            float v1 = s1.x - C[32];
            float zn0 = C[27] * v0 + C[28] * v1;
            float zn1 = C[29] * v0 + C[30] * v1;
            ldr -= C[33];
            if (C[34] != 0.f) { float t = zn0; zn0 = zn1; zn1 = t; }
            z0r = zn0; z1r = zn1;
        }
        __syncthreads();
    }

    if (lead) {
        out[2 * g]     = z0r;
        out[2 * g + 1] = z1r;
        out[(long)2 * B + g] = ldr;
    }
}

extern "C" void kernel_launch(void* const* d_in, const int* in_sizes, int n_in,
                              void* d_out, int out_size) {
    const float* z_0      = (const float*)d_in[0];
    const float* x        = (const float*)d_in[1];
    const float* sigma    = (const float*)d_in[2];
    const float* n1_w1    = (const float*)d_in[3];
    const float* n1_b1    = (const float*)d_in[4];
    const float* n1_w2    = (const float*)d_in[5];
    const float* n1_b2    = (const float*)d_in[6];
    const float* n2_w1    = (const float*)d_in[7];
    const float* n2_b1    = (const float*)d_in[8];
    const float* n2_w2    = (const float*)d_in[9];
    const float* n2_b2    = (const float*)d_in[10];
    const float* made_W0  = (const float*)d_in[11];
    const float* made_b0  = (const float*)d_in[12];
    const float* made_Wres= (const float*)d_in[13];
    const float* made_bres= (const float*)d_in[14];
    const float* made_Wf  = (const float*)d_in[15];
    const float* made_bf  = (const float*)d_in[16];
    const float* lu_lower = (const float*)d_in[17];
    const float* lu_upper = (const float*)d_in[18];
    const float* lu_diag  = (const float*)d_in[19];
    const float* lu_bias  = (const float*)d_in[20];
    const int*   perms    = (const int*)d_in[21];

    int B = in_sizes[0] / 2;

    precompute_consts_kernel<<<1, 32>>>(made_bf, lu_lower, lu_upper, lu_diag, lu_bias, perms);
    pack_weights_kernel<<<NMM, 256>>>(made_Wres, made_Wf);

    cudaFuncSetAttribute(nsf_mma_kernel, cudaFuncAttributeMaxDynamicSharedMemorySize, SM_TOTAL);
    int grid = (B + BT - 1) / BT;
    nsf_mma_kernel<<<grid, 256, SM_TOTAL>>>(z_0, x, sigma,
                                            n1_w1, n1_b1, n1_w2, n1_b2,
                                            n2_w1, n2_b1, n2_w2, n2_b2,
                                            made_W0, made_b0, made_bres,
                                            made_bf,
                                            (float*)d_out, B);
}